// round 11
// baseline (speedup 1.0000x reference)
#include <cuda_runtime.h>
#include <cuda_fp16.h>
#include <cstdint>

// Problem constants
#define BATCH 4
#define SEQ   2048
#define DMODEL 1024
#define NHEAD 16
#define DHEAD 64
#define MROWS (BATCH * SEQ)                       // 8192
#define OUT_ELEMS ((size_t)BATCH * SEQ * DMODEL)  // 8388608
#define GK 2048                                   // fp16 2-term K (2 x 1024)
#define SK 128                                    // fp16 2-term K for scores
#define NZ (BATCH * NHEAD)                        // 64 head-slices
#define VK 4096                                   // fp16 2-term K_eff for AV

// ---------------------------------------------------------------------------
// Scratch (device globals; allocation-free rule)
// ---------------------------------------------------------------------------
__device__ __half g_qs [(size_t)MROWS * GK];    // activations [hi | lo]
__device__ __half g_ks [(size_t)MROWS * GK];
__device__ __half g_vs [(size_t)MROWS * GK];
__device__ __half g_ohs[(size_t)MROWS * GK];
__device__ __half g_wqs[(size_t)DMODEL * GK];   // weights^T [hi | hi]
__device__ __half g_wks[(size_t)DMODEL * GK];
__device__ __half g_wvs[(size_t)DMODEL * GK];
__device__ __half g_wos[(size_t)DMODEL * GK];
__device__ __half g_qsp[(size_t)NZ * SEQ * SK]; // Q heads [hi|lo], pre-scaled 0.125
__device__ __half g_ksp[(size_t)NZ * SEQ * SK]; // K heads [hi|hi]
__device__ __half g_vsp[(size_t)NZ * DHEAD * VK]; // V^T, per-32-chunk [hi|hi]
__device__ __half g_eh [(size_t)NZ * SEQ * SEQ]; // unnormalized exp(score), fp16

// ---------------------------------------------------------------------------
// MMA / async-copy helpers
// ---------------------------------------------------------------------------
__device__ __forceinline__ uint32_t smem_u32(const void* p) {
    uint32_t a;
    asm("{ .reg .u64 t; cvta.to.shared.u64 t, %1; cvt.u32.u64 %0, t; }"
        : "=r"(a) : "l"(p));
    return a;
}

#define LDSM_X4(r0, r1, r2, r3, addr)                                          \
    asm volatile("ldmatrix.sync.aligned.m8n8.x4.shared.b16 {%0,%1,%2,%3}, [%4];" \
                 : "=r"(r0), "=r"(r1), "=r"(r2), "=r"(r3) : "r"(addr))

#define MMA16816(d, a, b)                                                      \
    asm volatile("mma.sync.aligned.m16n8k16.row.col.f32.f16.f16.f32 "          \
                 "{%0,%1,%2,%3}, {%4,%5,%6,%7}, {%8,%9}, {%0,%1,%2,%3};"       \
                 : "+f"((d)[0]), "+f"((d)[1]), "+f"((d)[2]), "+f"((d)[3])      \
                 : "r"((a)[0]), "r"((a)[1]), "r"((a)[2]), "r"((a)[3]),         \
                   "r"((b)[0]), "r"((b)[1]))

#define CP_ASYNC16(dst, src)                                                   \
    asm volatile("cp.async.cg.shared.global [%0], [%1], 16;"                   \
                 :: "r"(dst), "l"(src))
#define CP_COMMIT() asm volatile("cp.async.commit_group;" ::: "memory")
#define CP_WAIT(n)  asm volatile("cp.async.wait_group %0;" :: "n"(n) : "memory")

__device__ __forceinline__ uint32_t pack_h2(__half a, __half b) {
    __half2 h = __halves2half2(a, b);
    return *(uint32_t*)&h;
}

// One pipeline stage of the 128x128 loop: A[128][40] then B[128][40] halves.
#define TSTAGE 20480u
#define MAIN_SMEM (3 * 20480)     // 61440

// Core loop: CTA 128x128, 8 warps (2Mx4N), K-step 32,
// 3-stage cp.async pipeline, ONE barrier per iteration. nIters >= 2.
__device__ __forceinline__ void mma_loop_128x128(
    char* smem, const __half* __restrict__ Abase,
    const __half* __restrict__ Bbase,
    int lda, int ldb, int nIters, float acc[4][4][4])
{
    const int tid  = threadIdx.x;
    const int lane = tid & 31;
    const int warp = tid >> 5;
    const int wm = (warp >> 2) * 64;
    const int wn = (warp & 3) * 32;

    const int grow = tid >> 2;
    const int gcol = (tid & 3) * 8;
    const __half* Ap = Abase + (size_t)grow * lda + gcol;
    const __half* Bp = Bbase + (size_t)grow * ldb + gcol;

    const uint32_t s0 = smem_u32(smem);
    const uint32_t aStOff = (uint32_t)(grow * 80 + gcol * 2);
    const uint32_t bStOff = 10240u + (uint32_t)(grow * 80 + gcol * 2);

    const int mrow  = lane & 15;
    const int kA    = (lane & 16) ? 16 : 0;
    const int nrow  = (lane & 7) + ((lane & 16) ? 8 : 0);
    const int kB    = (lane & 8) ? 16 : 0;
    const uint32_t aLdm = s0 + (uint32_t)((wm + mrow) * 80 + kA);
    const uint32_t bLdm = s0 + 10240u + (uint32_t)((wn + nrow) * 80 + kB);

#define ISSUE_TILE(g)                                                          \
    do {                                                                       \
        const uint32_t st = s0 + (uint32_t)((g) % 3) * TSTAGE;                 \
        const __half* An = Ap + (g) * 32;                                      \
        const __half* Bn = Bp + (g) * 32;                                      \
        CP_ASYNC16(st + aStOff, An);                                           \
        CP_ASYNC16(st + aStOff + 64u * 80u, An + (size_t)64 * lda);            \
        CP_ASYNC16(st + bStOff, Bn);                                           \
        CP_ASYNC16(st + bStOff + 64u * 80u, Bn + (size_t)64 * ldb);            \
        CP_COMMIT();                                                           \
    } while (0)

    ISSUE_TILE(0);
    ISSUE_TILE(1);

    for (int it = 0; it < nIters; ++it) {
        if (it + 1 < nIters) { CP_WAIT(1); } else { CP_WAIT(0); }
        __syncthreads();
        if (it + 2 < nIters) ISSUE_TILE(it + 2);

        const uint32_t cur = (uint32_t)(it % 3) * TSTAGE;
#pragma unroll
        for (int ks = 0; ks < 2; ++ks) {
            uint32_t a[4][4], b[4][2];
#pragma unroll
            for (int mi = 0; mi < 4; ++mi)
                LDSM_X4(a[mi][0], a[mi][1], a[mi][2], a[mi][3],
                        aLdm + cur + (uint32_t)(mi * 16 * 80 + ks * 32));
            LDSM_X4(b[0][0], b[0][1], b[1][0], b[1][1],
                    bLdm + cur + (uint32_t)(ks * 32));
            LDSM_X4(b[2][0], b[2][1], b[3][0], b[3][1],
                    bLdm + cur + (uint32_t)(16 * 80 + ks * 32));
#pragma unroll
            for (int mi = 0; mi < 4; ++mi)
#pragma unroll
                for (int ni = 0; ni < 4; ++ni)
                    MMA16816(acc[mi][ni], a[mi], b[ni]);
        }
    }
#undef ISSUE_TILE
}

// ---------------------------------------------------------------------------
// Merged Q/K/V projection: grid (8, 64, 3). z=0:Q, z=1:K, z=2:V.
// ---------------------------------------------------------------------------
struct QKVArgs {
    const __half* A[3];
    const __half* W[3];
    const float*  bias[3];
    __half*       C[3];
};

__global__ __launch_bounds__(256) void proj_qkv(QKVArgs args)
{
    extern __shared__ char smem[];
    const int zk = blockIdx.z;       // 0=Q, 1=K, 2=V
    const int mbase = blockIdx.y * 128;
    const int nbase = blockIdx.x * 128;

    const __half* Ag = args.A[zk];
    const __half* Bg = args.W[zk];
    const float* bias = args.bias[zk];
    __half* Cs = args.C[zk];

    float acc[4][4][4];
#pragma unroll
    for (int i = 0; i < 4; i++)
#pragma unroll
        for (int j = 0; j < 4; j++)
#pragma unroll
            for (int r = 0; r < 4; r++) acc[i][j][r] = 0.0f;

    mma_loop_128x128(smem, Ag + (size_t)mbase * GK, Bg + (size_t)nbase * GK,
                     GK, GK, GK / 32, acc);

    const int lane = threadIdx.x & 31;
    const int warp = threadIdx.x >> 5;
    const int wm = (warp >> 2) * 64;
    const int wn = (warp & 3) * 32;
    const int g = lane >> 2, tg = lane & 3;

#pragma unroll
    for (int mi = 0; mi < 4; ++mi) {
#pragma unroll
        for (int ni = 0; ni < 4; ++ni) {
#pragma unroll
            for (int half = 0; half < 2; ++half) {
                const int m = mbase + wm + mi * 16 + g + half * 8;
                const int n0 = nbase + wn + ni * 8 + tg * 2;
                float v0 = acc[mi][ni][half * 2 + 0] + bias[n0];
                float v1 = acc[mi][ni][half * 2 + 1] + bias[n0 + 1];
                const int z = ((m >> 11) << 4) + (n0 >> 6);
                const int s = m & (SEQ - 1);
                const int d = n0 & 63;
                if (zk == 0) { v0 *= 0.125f; v1 *= 0.125f; }
                const __half h0 = __float2half_rn(v0);
                const __half h1 = __float2half_rn(v1);
                if (zk == 0) {           // Q: [hi | lo], pre-scaled
                    const __half l0 = __float2half_rn(v0 - __half2float(h0));
                    const __half l1 = __float2half_rn(v1 - __half2float(h1));
                    __half* p = Cs + ((size_t)z * SEQ + s) * SK;
                    *(uint32_t*)(p + d)      = pack_h2(h0, h1);
                    *(uint32_t*)(p + 64 + d) = pack_h2(l0, l1);
                } else if (zk == 1) {    // K: [hi | hi]
                    __half* p = Cs + ((size_t)z * SEQ + s) * SK;
                    const uint32_t hh = pack_h2(h0, h1);
                    *(uint32_t*)(p + d)      = hh;
                    *(uint32_t*)(p + 64 + d) = hh;
                } else {                 // V^T: per-32-chunk [hi | hi]
                    const size_t b0 =
                        ((size_t)z * DHEAD + d) * VK + 64 * (s >> 5) + (s & 31);
                    Cs[b0]       = h0;
                    Cs[b0 + 32]  = h0;
                    const size_t b1 = b0 + VK;   // d+1 row
                    Cs[b1]       = h1;
                    Cs[b1 + 32]  = h1;
                }
            }
        }
    }
}

// ---------------------------------------------------------------------------
// Output projection: D[8192,1024] fp32 = ohs[8192,2048] x wos[1024,2048]^T + bias
// ---------------------------------------------------------------------------
__global__ __launch_bounds__(256) void proj_out(
    const __half* __restrict__ Ag, const __half* __restrict__ Bg,
    const float* __restrict__ bias, float* __restrict__ Cf)
{
    extern __shared__ char smem[];
    const int mbase = blockIdx.y * 128;
    const int nbase = blockIdx.x * 128;

    float acc[4][4][4];
#pragma unroll
    for (int i = 0; i < 4; i++)
#pragma unroll
        for (int j = 0; j < 4; j++)
#pragma unroll
            for (int r = 0; r < 4; r++) acc[i][j][r] = 0.0f;

    mma_loop_128x128(smem, Ag + (size_t)mbase * GK, Bg + (size_t)nbase * GK,
                     GK, GK, GK / 32, acc);

    const int lane = threadIdx.x & 31;
    const int warp = threadIdx.x >> 5;
    const int wm = (warp >> 2) * 64;
    const int wn = (warp & 3) * 32;
    const int g = lane >> 2, tg = lane & 3;

#pragma unroll
    for (int mi = 0; mi < 4; ++mi) {
#pragma unroll
        for (int ni = 0; ni < 4; ++ni) {
#pragma unroll
            for (int half = 0; half < 2; ++half) {
                const int m = mbase + wm + mi * 16 + g + half * 8;
                const int n0 = nbase + wn + ni * 8 + tg * 2;
                float v0 = acc[mi][ni][half * 2 + 0] + bias[n0];
                float v1 = acc[mi][ni][half * 2 + 1] + bias[n0 + 1];
                *(float2*)&Cf[(size_t)m * DMODEL + n0] = make_float2(v0, v1);
            }
        }
    }
}

// ---------------------------------------------------------------------------
// Fused attention: per CTA = (z, 128 q-rows), 512 threads (16 warps).
// Loop over 16 k-tiles: S=Q@K^T -> exp (e->gmem fp16, rowsums) ->
// P [hi|lo] in smem -> O += P@V (unnormalized). Epilogue: normalize O -> ohs,
// stream attn = e * inv (fp32 output).
//
// smem: Q 4x[128][40] | K 4x[128][40] | V 8x[64][40] | P 8x[128][40]
//       | rowpart f[4][128] | rowsum f[128]
// ---------------------------------------------------------------------------
#define SM_Q 0u
#define SM_K 40960u
#define SM_V 81920u
#define SM_P 122880u
#define SM_RP 204800u
#define SM_RS 206848u
#define FUSED_SMEM 207360

__global__ __launch_bounds__(512) void attn_fused(
    const __half* __restrict__ qsp, const __half* __restrict__ ksp,
    const __half* __restrict__ vsp,
    __half* __restrict__ eh, float* __restrict__ attn,
    __half* __restrict__ ohs)
{
    extern __shared__ char smem[];
    const uint32_t s0 = smem_u32(smem);
    const int z = blockIdx.y;
    const int qbase = blockIdx.x * 128;
    const int b = z >> 4, h = z & 15;
    const int tid = threadIdx.x, lane = tid & 31, warp = tid >> 5;
    const int wmS = (warp >> 2) * 32;      // M group (shared S/AV)
    const int wnS = (warp & 3) * 32;       // S n-offset
    const int wnA = (warp & 3) * 16;       // AV n-offset
    const int g = lane >> 2, tg = lane & 3;
    const int mrow = lane & 15;
    const int kA = (lane & 16) ? 16 : 0;
    const int nrow = (lane & 7) + ((lane & 16) ? 8 : 0);
    const int kB = (lane & 8) ? 16 : 0;

    float* rowpart = (float*)(smem + SM_RP);   // [4][128]
    float* rowsum  = (float*)(smem + SM_RS);   // [128]
    if (tid < 128) rowsum[tid] = 0.0f;

    const __half* Qg = qsp + ((size_t)z * SEQ + qbase) * SK;
    const __half* Kg = ksp + (size_t)z * SEQ * SK;
    const __half* Vg = vsp + (size_t)z * DHEAD * VK;
    __half* Eg = eh + ((size_t)z * SEQ + qbase) * SEQ;

    // Prologue: group A0 = {Q, K0}; group B0 = {V0}
#pragma unroll
    for (int i = 0; i < 4; ++i) {
        const int idx = tid + i * 512;
        const int r = idx >> 4, j = idx & 15;
        CP_ASYNC16(s0 + SM_Q + (uint32_t)((j >> 2) * 10240 + r * 80 + (j & 3) * 16),
                   Qg + (size_t)r * SK + j * 8);
    }
#pragma unroll
    for (int i = 0; i < 4; ++i) {
        const int idx = tid + i * 512;
        const int r = idx >> 4, j = idx & 15;
        CP_ASYNC16(s0 + SM_K + (uint32_t)((j >> 2) * 10240 + r * 80 + (j & 3) * 16),
                   Kg + (size_t)r * SK + j * 8);
    }
    CP_COMMIT();
#pragma unroll
    for (int i = 0; i < 4; ++i) {
        const int idx = tid + i * 512;
        const int d = idx >> 5, j = idx & 31;
        CP_ASYNC16(s0 + SM_V + (uint32_t)((j >> 2) * 5120 + d * 80 + (j & 3) * 16),
                   Vg + (size_t)d * VK + j * 8);
    }
    CP_COMMIT();

    // LDSM bases
    const uint32_t aQ = s0 + SM_Q + (uint32_t)((wmS + mrow) * 80 + kA);
    const uint32_t bK = s0 + SM_K + (uint32_t)((wnS + nrow) * 80 + kB);
    const uint32_t aP = s0 + SM_P + (uint32_t)((wmS + mrow) * 80 + kA);
    const uint32_t bV = s0 + SM_V + (uint32_t)((wnA + nrow) * 80 + kB);

    float acc_o[2][2][4];
#pragma unroll
    for (int i = 0; i < 2; i++)
#pragma unroll
        for (int j = 0; j < 2; j++)
#pragma unroll
            for (int r = 0; r < 4; r++) acc_o[i][j][r] = 0.0f;

    for (int kt = 0; kt < 16; ++kt) {
        CP_WAIT(1);               // K(kt) (+Q first iter) ready; V(kt) may pend
        __syncthreads();

        // ---- S = Q @ K(kt)^T  (128x128, K=128) ----
        float acc_s[2][4][4];
#pragma unroll
        for (int i = 0; i < 2; i++)
#pragma unroll
            for (int j = 0; j < 4; j++)
#pragma unroll
                for (int r = 0; r < 4; r++) acc_s[i][j][r] = 0.0f;

#pragma unroll
        for (int c = 0; c < 4; ++c) {
#pragma unroll
            for (int ks = 0; ks < 2; ++ks) {
                uint32_t a[2][4], bq[4][2];
#pragma unroll
                for (int mi = 0; mi < 2; ++mi)
                    LDSM_X4(a[mi][0], a[mi][1], a[mi][2], a[mi][3],
                            aQ + (uint32_t)(c * 10240 + mi * 16 * 80 + ks * 32));
                LDSM_X4(bq[0][0], bq[0][1], bq[1][0], bq[1][1],
                        bK + (uint32_t)(c * 10240 + ks * 32));
                LDSM_X4(bq[2][0], bq[2][1], bq[3][0], bq[3][1],
                        bK + (uint32_t)(c * 10240 + 16 * 80 + ks * 32));
#pragma unroll
                for (int mi = 0; mi < 2; ++mi)
#pragma unroll
                    for (int ni = 0; ni < 4; ++ni)
                        MMA16816(acc_s[mi][ni], a[mi], bq[ni]);
            }
        }
        __syncthreads();          // everyone done reading K smem

        // prefetch K(kt+1) into the (single) K buffer; always commit
        if (kt + 1 < 16) {
#pragma unroll
            for (int i = 0; i < 4; ++i) {
                const int idx = tid + i * 512;
                const int r = idx >> 4, j = idx & 15;
                CP_ASYNC16(s0 + SM_K + (uint32_t)((j >> 2) * 10240 + r * 80 + (j & 3) * 16),
                           Kg + (size_t)((kt + 1) * 128 + r) * SK + j * 8);
            }
        }
        CP_COMMIT();

        // ---- exp, e -> gmem, rowsums, P [hi|lo] -> smem ----
#pragma unroll
        for (int mi = 0; mi < 2; ++mi) {
#pragma unroll
            for (int half = 0; half < 2; ++half) {
                const int row = wmS + mi * 16 + g + half * 8;
                float s8 = 0.0f;
#pragma unroll
                for (int ni = 0; ni < 4; ++ni) {
                    const int c = wnS + ni * 8 + tg * 2;
                    const float e0 = __expf(acc_s[mi][ni][half * 2 + 0]);
                    const float e1 = __expf(acc_s[mi][ni][half * 2 + 1]);
                    const __half h0 = __float2half_rn(e0);
                    const __half h1 = __float2half_rn(e1);
                    *(uint32_t*)&Eg[(size_t)row * SEQ + kt * 128 + c] =
                        pack_h2(h0, h1);
                    const float f0 = __half2float(h0);
                    const float f1 = __half2float(h1);
                    s8 += f0 + f1;
                    const __half l0 = __float2half_rn(e0 - f0);
                    const __half l1 = __float2half_rn(e1 - f1);
                    char* pp = smem + SM_P + (c >> 5) * 20480 + row * 80 + (c & 31) * 2;
                    *(uint32_t*)pp           = pack_h2(h0, h1);   // sub 2c: hi
                    *(uint32_t*)(pp + 10240) = pack_h2(l0, l1);   // sub 2c+1: lo
                }
                s8 += __shfl_xor_sync(0xffffffffu, s8, 1);
                s8 += __shfl_xor_sync(0xffffffffu, s8, 2);
                if (tg == 0) rowpart[(warp & 3) * 128 + row] = s8;
            }
        }

        CP_WAIT(1);               // V(kt) ready (only K(kt+1) may pend)
        __syncthreads();          // publish P + rowpart; V visible

        if (tid < 128)
            rowsum[tid] += (rowpart[tid] + rowpart[128 + tid])
                         + (rowpart[256 + tid] + rowpart[384 + tid]);

        // ---- O += P @ V  (128x64, K_eff=256) ----
#pragma unroll
        for (int sub = 0; sub < 8; ++sub) {
#pragma unroll
            for (int ks = 0; ks < 2; ++ks) {
                uint32_t a[2][4], bq[2][2];
#pragma unroll
                for (int mi = 0; mi < 2; ++mi)
                    LDSM_X4(a[mi][0], a[mi][1], a[mi][2], a[mi][3],
                            aP + (uint32_t)(sub * 10240 + mi * 16 * 80 + ks * 32));
                LDSM_X4(bq[0][0], bq[0][1], bq[1][0], bq[1][1],
                        bV + (uint32_t)(sub * 5120 + ks * 32));
#pragma unroll
                for (int mi = 0; mi < 2; ++mi)
#pragma unroll
                    for (int ni = 0; ni < 2; ++ni)
                        MMA16816(acc_o[mi][ni], a[mi], bq[ni]);
            }
        }
        __syncthreads();          // everyone done reading P & V smem

        // prefetch V(kt+1); always commit
        if (kt + 1 < 16) {
#pragma unroll
            for (int i = 0; i < 4; ++i) {
                const int idx = tid + i * 512;
                const int d = idx >> 5, j = idx & 31;
                CP_ASYNC16(s0 + SM_V + (uint32_t)((j >> 2) * 5120 + d * 80 + (j & 3) * 16),
                           Vg + (size_t)d * VK + (kt + 1) * 256 + j * 8);
            }
        }
        CP_COMMIT();
    }

    __syncthreads();
    if (tid < 128) rowsum[tid] = 1.0f / rowsum[tid];
    __syncthreads();

    // ---- O epilogue: normalize, write ohs [hi|lo] ----
#pragma unroll
    for (int mi = 0; mi < 2; ++mi) {
#pragma unroll
        for (int ni = 0; ni < 2; ++ni) {
#pragma unroll
            for (int half = 0; half < 2; ++half) {
                const int row = wmS + mi * 16 + g + half * 8;
                const int col = wnA + ni * 8 + tg * 2;
                const float inv = rowsum[row];
                const float v0 = acc_o[mi][ni][half * 2 + 0] * inv;
                const float v1 = acc_o[mi][ni][half * 2 + 1] * inv;
                const __half h0 = __float2half_rn(v0);
                const __half l0 = __float2half_rn(v0 - __half2float(h0));
                const __half h1 = __float2half_rn(v1);
                const __half l1 = __float2half_rn(v1 - __half2float(h1));
                __half* p = ohs + (size_t)(b * SEQ + qbase + row) * GK + h * DHEAD + col;
                *(uint32_t*)p          = pack_h2(h0, h1);
                *(uint32_t*)(p + 1024) = pack_h2(l0, l1);
            }
        }
    }

    // ---- attn output: p = e * inv (fp32), streaming from L2-hot e ----
    float* Pout = attn + ((size_t)z * SEQ + qbase) * SEQ;
#pragma unroll 4
    for (int i = 0; i < 64; ++i) {
        const int idx = tid + i * 512;
        const int row = idx >> 8;            // 256 uint4 per 2048-col row
        const int cc = (idx & 255) * 8;
        const float inv = rowsum[row];
        const uint4 ev = *(const uint4*)&Eg[(size_t)row * SEQ + cc];
        const __half2* e2 = (const __half2*)&ev;
        float2 f0 = __half22float2(e2[0]);
        float2 f1 = __half22float2(e2[1]);
        float2 f2 = __half22float2(e2[2]);
        float2 f3 = __half22float2(e2[3]);
        float* pw = &Pout[(size_t)row * SEQ + cc];
        *(float4*)pw       = make_float4(f0.x * inv, f0.y * inv, f1.x * inv, f1.y * inv);
        *(float4*)(pw + 4) = make_float4(f2.x * inv, f2.y * inv, f3.x * inv, f3.y * inv);
    }
}

// ---------------------------------------------------------------------------
// Merged prep_act: grid (total4/256, 3). X[R,1024] fp32 -> Y[R,2048] [hi|lo]
// ---------------------------------------------------------------------------
struct PrepActArgs { const float* X[3]; __half* Y[3]; };

__global__ __launch_bounds__(256) void prep_act3(PrepActArgs args)
{
    const float* X = args.X[blockIdx.y];
    __half* Y = args.Y[blockIdx.y];
    int i = blockIdx.x * 256 + threadIdx.x;
    float4 xv = ((const float4*)X)[i];
    int r = i >> 8;
    int k = (i & 255) * 4;
    __half* p = Y + (size_t)r * GK + k;

    float xs[4] = {xv.x, xv.y, xv.z, xv.w};
    __half hi[4], lo[4];
#pragma unroll
    for (int j = 0; j < 4; j++) {
        hi[j] = __float2half_rn(xs[j]);
        lo[j] = __float2half_rn(xs[j] - __half2float(hi[j]));
    }
    *(uint32_t*)(p)          = pack_h2(hi[0], hi[1]);
    *(uint32_t*)(p + 2)      = pack_h2(hi[2], hi[3]);
    *(uint32_t*)(p + 1024)   = pack_h2(lo[0], lo[1]);
    *(uint32_t*)(p + 1026)   = pack_h2(lo[2], lo[3]);
}

// ---------------------------------------------------------------------------
// Merged prep_wgt: grid (32, 32, 4). W[1024,1024] -> Ws[N=1024,2048] [hi|hi]
// ---------------------------------------------------------------------------
struct PrepWgtArgs { const float* W[4]; __half* Ws[4]; };

__global__ __launch_bounds__(256) void prep_wgt4(PrepWgtArgs args)
{
    const float* W = args.W[blockIdx.z];
    __half* Ws = args.Ws[blockIdx.z];
    __shared__ float t[32][33];
    const int k0 = blockIdx.y * 32, n0 = blockIdx.x * 32;
    const int tx = threadIdx.x, ty = threadIdx.y;   // (32, 8)
#pragma unroll
    for (int r = ty; r < 32; r += 8)
        t[r][tx] = W[(size_t)(k0 + r) * DMODEL + n0 + tx];
    __syncthreads();
#pragma unroll
    for (int r = ty; r < 32; r += 8) {
        const int n = n0 + r;
        const int k = k0 + tx;
        const __half hi = __float2half_rn(t[tx][r]);
        __half* p = Ws + (size_t)n * GK;
        p[k]        = hi;
        p[1024 + k] = hi;
    }
}

// ---------------------------------------------------------------------------
extern "C" void kernel_launch(void* const* d_in, const int* in_sizes, int n_in,
                              void* d_out, int out_size)
{
    const float* q  = (const float*)d_in[0];
    const float* k  = (const float*)d_in[1];
    const float* v  = (const float*)d_in[2];
    const float* Wq = (const float*)d_in[3];
    const float* bq = (const float*)d_in[4];
    const float* Wk = (const float*)d_in[5];
    const float* bk = (const float*)d_in[6];
    const float* Wv = (const float*)d_in[7];
    const float* bv = (const float*)d_in[8];
    const float* Wo = (const float*)d_in[9];
    const float* bo = (const float*)d_in[10];

    float* out  = (float*)d_out;
    float* attn = out + OUT_ELEMS;

    __half *qs, *ks, *vs, *ohs, *wqs, *wks, *wvs, *wos, *qsp, *ksp, *vsp, *ehp;
    cudaGetSymbolAddress((void**)&qs,  g_qs);
    cudaGetSymbolAddress((void**)&ks,  g_ks);
    cudaGetSymbolAddress((void**)&vs,  g_vs);
    cudaGetSymbolAddress((void**)&ohs, g_ohs);
    cudaGetSymbolAddress((void**)&wqs, g_wqs);
    cudaGetSymbolAddress((void**)&wks, g_wks);
    cudaGetSymbolAddress((void**)&wvs, g_wvs);
    cudaGetSymbolAddress((void**)&wos, g_wos);
    cudaGetSymbolAddress((void**)&qsp, g_qsp);
    cudaGetSymbolAddress((void**)&ksp, g_ksp);
    cudaGetSymbolAddress((void**)&vsp, g_vsp);
    cudaGetSymbolAddress((void**)&ehp, g_eh);

    cudaFuncSetAttribute(proj_qkv,   cudaFuncAttributeMaxDynamicSharedMemorySize, MAIN_SMEM);
    cudaFuncSetAttribute(proj_out,   cudaFuncAttributeMaxDynamicSharedMemorySize, MAIN_SMEM);
    cudaFuncSetAttribute(attn_fused, cudaFuncAttributeMaxDynamicSharedMemorySize, FUSED_SMEM);

    const int act4 = MROWS * DMODEL / 4;   // 2097152 -> 8192 blocks

    // 0) fp16 2-term conversions (merged launches)
    PrepWgtArgs wargs;
    wargs.W[0] = Wq; wargs.W[1] = Wk; wargs.W[2] = Wv; wargs.W[3] = Wo;
    wargs.Ws[0] = wqs; wargs.Ws[1] = wks; wargs.Ws[2] = wvs; wargs.Ws[3] = wos;
    prep_wgt4<<<dim3(32, 32, 4), dim3(32, 8)>>>(wargs);

    PrepActArgs aargs;
    aargs.X[0] = q; aargs.X[1] = k; aargs.X[2] = v;
    aargs.Y[0] = qs; aargs.Y[1] = ks; aargs.Y[2] = vs;
    prep_act3<<<dim3(act4 / 256, 3), 256>>>(aargs);

    // 1) Q/K/V projections merged (HMMA): grid (8, 64, 3)
    QKVArgs pargs;
    pargs.A[0] = qs;  pargs.A[1] = ks;  pargs.A[2] = vs;
    pargs.W[0] = wqs; pargs.W[1] = wks; pargs.W[2] = wvs;
    pargs.bias[0] = bq; pargs.bias[1] = bk; pargs.bias[2] = bv;
    pargs.C[0] = qsp; pargs.C[1] = ksp; pargs.C[2] = vsp;
    proj_qkv<<<dim3(DMODEL / 128, MROWS / 128, 3), 256, MAIN_SMEM>>>(pargs);

    // 2) Fused attention: scores + softmax + AV + attn output
    attn_fused<<<dim3(SEQ / 128, NZ), 512, FUSED_SMEM>>>(
        qsp, ksp, vsp, ehp, attn, ohs);

    // 3) Output projection -> d_out
    proj_out<<<dim3(DMODEL / 128, MROWS / 128), 256, MAIN_SMEM>>>(ohs, wos, bo, out);
}